// round 2
// baseline (speedup 1.0000x reference)
#include <cuda_runtime.h>

#define B_TOT 4096
#define T_LEN 512
#define D_IN  5
#define NB    32          // batches per CTA
#define NTHR  512         // 16 warps, 4 per SMSP
#define HS    36          // padded row stride (floats) for h/x state

// shared memory layout (float offsets)
#define OFF_WHH0 0
#define OFF_WIH1 16384
#define OFF_WHH1 32768
#define OFF_WIH0 49152                 // 5*64*4 = 1280
#define OFF_H0A  (49152 + 1280)        // 64*36 = 2304 (h0 buffer 0)
#define OFF_H0B  (OFF_H0A + 2304)      // h0 buffer 1
#define OFF_H1   (OFF_H0B + 2304)
#define OFF_XA   (OFF_H1 + 2304)       // 5*36 = 180 (x buffer 0)
#define OFF_XB   (OFF_XA + 180)
#define SMEM_FLOATS (OFF_XB + 180)     // 57,704 floats
#define SMEM_BYTES  (SMEM_FLOATS * 4)  // 230,816 B (< 232,448 dyn limit)

typedef unsigned long long u64;

union F2U { float2 f; u64 u; };

__device__ __forceinline__ u64 dup2(float x) {
    F2U t; t.f = make_float2(x, x); return t.u;
}
__device__ __forceinline__ float2 unpk(u64 v) {
    F2U t; t.u = v; return t.f;
}
// packed fp32x2 FMA: a.lo += x.lo*w.lo ; a.hi += x.hi*w.hi
__device__ __forceinline__ void fma2(u64& a, u64 x, u64 w) {
    asm("fma.rn.f32x2 %0, %1, %2, %0;" : "+l"(a) : "l"(x), "l"(w));
}

// MUFU.TANH — 1 MUFU op, used for the bounded gate sigmoids
__device__ __forceinline__ float tanha(float x) {
    float y; asm("tanh.approx.f32 %0, %1;" : "=f"(y) : "f"(x)); return y;
}
__device__ __forceinline__ float sigf(float x) {
    return fmaf(0.5f, tanha(0.5f * x), 0.5f);
}
// exact-ish tanh for the recurrent payload path (g, tanh(c))
__device__ __forceinline__ float tanh_acc(float x) {
    return 1.0f - __fdividef(2.0f, __expf(2.0f * x) + 1.0f);
}

__global__ void __launch_bounds__(NTHR, 1)
stocklstm_kernel(const float* __restrict__ x,
                 const float* __restrict__ W_ih0, const float* __restrict__ W_hh0,
                 const float* __restrict__ b_ih0, const float* __restrict__ b_hh0,
                 const float* __restrict__ W_ih1, const float* __restrict__ W_hh1,
                 const float* __restrict__ b_ih1, const float* __restrict__ b_hh1,
                 const float* __restrict__ W1,   const float* __restrict__ b1,
                 const float* __restrict__ W2,   const float* __restrict__ b2,
                 float* __restrict__ out)
{
    extern __shared__ float sm[];
    float* whh0 = sm + OFF_WHH0;
    float* wih1 = sm + OFF_WIH1;
    float* whh1 = sm + OFF_WHH1;
    float* wih0 = sm + OFF_WIH0;
    float* h0buf[2] = { sm + OFF_H0A, sm + OFF_H0B };
    float* h1s  = sm + OFF_H1;
    float* xbuf[2] = { sm + OFF_XA, sm + OFF_XB };

    const int tid = threadIdx.x;
    const int j   = tid & 63;   // hidden unit index
    const int bg  = tid >> 6;   // batch group 0..7
    const int bb  = bg * 4;     // first batch (of 4) this thread owns
    const int B0  = blockIdx.x * NB;

    // ---- stage weights, packed [k][j][4 gates] for conflict-free LDS.128 ----
    for (int idx = tid; idx < 256 * 64; idx += NTHR) {
        int g = idx >> 6, k = idx & 63;          // global row-major [G][64]
        int gi = g >> 6, jj = g & 63;            // gate type, unit
        int dst = (k * 64 + jj) * 4 + gi;
        whh0[dst] = W_hh0[idx];
        wih1[dst] = W_ih1[idx];
        whh1[dst] = W_hh1[idx];
    }
    for (int idx = tid; idx < 256 * 5; idx += NTHR) {
        int g = idx / 5, d = idx - 5 * g;
        wih0[(d * 64 + (g & 63)) * 4 + (g >> 6)] = W_ih0[idx];
    }
    for (int idx = tid; idx < 64 * HS; idx += NTHR) {
        h0buf[0][idx] = 0.0f; h1s[idx] = 0.0f;
    }

    // bias pre-sums (b_ih + b_hh), duplicated into both f32x2 lanes
    const u64 bi0 = dup2(b_ih0[j]       + b_hh0[j]);
    const u64 bf0 = dup2(b_ih0[64 + j]  + b_hh0[64 + j]);
    const u64 bg0 = dup2(b_ih0[128 + j] + b_hh0[128 + j]);
    const u64 bo0 = dup2(b_ih0[192 + j] + b_hh0[192 + j]);
    const u64 bi1 = dup2(b_ih1[j]       + b_hh1[j]);
    const u64 bf1 = dup2(b_ih1[64 + j]  + b_hh1[64 + j]);
    const u64 bg1 = dup2(b_ih1[128 + j] + b_hh1[128 + j]);
    const u64 bo1 = dup2(b_ih1[192 + j] + b_hh1[192 + j]);

    float c0[4], c1[4];
#pragma unroll
    for (int p = 0; p < 4; p++) { c0[p] = 0.0f; c1[p] = 0.0f; }

    // ---- x staging: threads 0..159 own (batch xbi, feature xd) ----
    const int xbi = tid / 5;
    const int xd  = tid - xbi * 5;
    const float* xptr = x + (size_t)(B0 + xbi) * (T_LEN * D_IN) + xd;
    float xreg = 0.0f;
    if (tid < 160) {
        xreg = xptr[0];
        xbuf[0][xd * HS + xbi] = xreg;           // stage x[0]
        xreg = xptr[D_IN];                       // prefetch x[1]
    }

    __syncthreads();

    for (int t = 0; t < T_LEN; t++) {
        const int cur = t & 1, nxt = cur ^ 1;
        const float* h0c = h0buf[cur];
        const float* xc  = xbuf[cur];

        // ================= Layer 0 gates (read xs[cur], h0[cur]) ==========
        u64 aI[2], aF[2], aG[2], aO[2];
        aI[0] = bi0; aI[1] = bi0; aF[0] = bf0; aF[1] = bf0;
        aG[0] = bg0; aG[1] = bg0; aO[0] = bo0; aO[1] = bo0;

#pragma unroll
        for (int d = 0; d < 5; d++) {
            float4 w = *(const float4*)&wih0[(d * 64 + j) * 4];
            u64 wi = dup2(w.x), wf = dup2(w.y), wg = dup2(w.z), wo = dup2(w.w);
            ulonglong2 xa = *(const ulonglong2*)&xc[d * HS + bb];
            fma2(aI[0], xa.x, wi); fma2(aI[1], xa.y, wi);
            fma2(aF[0], xa.x, wf); fma2(aF[1], xa.y, wf);
            fma2(aG[0], xa.x, wg); fma2(aG[1], xa.y, wg);
            fma2(aO[0], xa.x, wo); fma2(aO[1], xa.y, wo);
        }
#pragma unroll 8
        for (int k = 0; k < 64; k++) {
            float4 w = *(const float4*)&whh0[(k * 64 + j) * 4];
            u64 wi = dup2(w.x), wf = dup2(w.y), wg = dup2(w.z), wo = dup2(w.w);
            ulonglong2 ha = *(const ulonglong2*)&h0c[k * HS + bb];
            fma2(aI[0], ha.x, wi); fma2(aI[1], ha.y, wi);
            fma2(aF[0], ha.x, wf); fma2(aF[1], ha.y, wf);
            fma2(aG[0], ha.x, wg); fma2(aG[1], ha.y, wg);
            fma2(aO[0], ha.x, wo); fma2(aO[1], ha.y, wo);
        }

        // pointwise L0 (c stays in registers)
        float hn[4];
#pragma unroll
        for (int p = 0; p < 2; p++) {
            float2 vi = unpk(aI[p]), vf = unpk(aF[p]), vg = unpk(aG[p]), vo = unpk(aO[p]);
            float ca = sigf(vf.x) * c0[2 * p]     + sigf(vi.x) * tanh_acc(vg.x);
            float cb = sigf(vf.y) * c0[2 * p + 1] + sigf(vi.y) * tanh_acc(vg.y);
            c0[2 * p] = ca; c0[2 * p + 1] = cb;
            hn[2 * p]     = sigf(vo.x) * tanh_acc(ca);
            hn[2 * p + 1] = sigf(vo.y) * tanh_acc(cb);
        }
        // write NEW h0 into the alternate buffer (no WAR hazard -> no sync)
        *(float4*)&h0buf[nxt][j * HS + bb] = make_float4(hn[0], hn[1], hn[2], hn[3]);

        // stage x[t+1] into alternate buffer; prefetch x[t+2]
        if (tid < 160) {
            xbuf[nxt][xd * HS + xbi] = xreg;
            int tn = (t + 2 < T_LEN) ? t + 2 : T_LEN - 1;
            xreg = xptr[tn * D_IN];
        }

        __syncthreads();   // S1: new h0 + new x visible; prev-iter h1 writes visible

        // ================= Layer 1 gates: recurrent (old h1) + input (new h0)
        aI[0] = bi1; aI[1] = bi1; aF[0] = bf1; aF[1] = bf1;
        aG[0] = bg1; aG[1] = bg1; aO[0] = bo1; aO[1] = bo1;

#pragma unroll 8
        for (int k = 0; k < 64; k++) {
            float4 w = *(const float4*)&whh1[(k * 64 + j) * 4];
            u64 wi = dup2(w.x), wf = dup2(w.y), wg = dup2(w.z), wo = dup2(w.w);
            ulonglong2 ha = *(const ulonglong2*)&h1s[k * HS + bb];
            fma2(aI[0], ha.x, wi); fma2(aI[1], ha.y, wi);
            fma2(aF[0], ha.x, wf); fma2(aF[1], ha.y, wf);
            fma2(aG[0], ha.x, wg); fma2(aG[1], ha.y, wg);
            fma2(aO[0], ha.x, wo); fma2(aO[1], ha.y, wo);
        }
        const float* h0n = h0buf[nxt];
#pragma unroll 8
        for (int k = 0; k < 64; k++) {
            float4 w = *(const float4*)&wih1[(k * 64 + j) * 4];
            u64 wi = dup2(w.x), wf = dup2(w.y), wg = dup2(w.z), wo = dup2(w.w);
            ulonglong2 ha = *(const ulonglong2*)&h0n[k * HS + bb];
            fma2(aI[0], ha.x, wi); fma2(aI[1], ha.y, wi);
            fma2(aF[0], ha.x, wf); fma2(aF[1], ha.y, wf);
            fma2(aG[0], ha.x, wg); fma2(aG[1], ha.y, wg);
            fma2(aO[0], ha.x, wo); fma2(aO[1], ha.y, wo);
        }

        // pointwise L1 (register-only; safe before the barrier)
#pragma unroll
        for (int p = 0; p < 2; p++) {
            float2 vi = unpk(aI[p]), vf = unpk(aF[p]), vg = unpk(aG[p]), vo = unpk(aO[p]);
            float ca = sigf(vf.x) * c1[2 * p]     + sigf(vi.x) * tanh_acc(vg.x);
            float cb = sigf(vf.y) * c1[2 * p + 1] + sigf(vi.y) * tanh_acc(vg.y);
            c1[2 * p] = ca; c1[2 * p + 1] = cb;
            hn[2 * p]     = sigf(vo.x) * tanh_acc(ca);
            hn[2 * p + 1] = sigf(vo.y) * tanh_acc(cb);
        }

        __syncthreads();   // S2: all reads of old h1 complete
        *(float4*)&h1s[j * HS + bb] = make_float4(hn[0], hn[1], hn[2], hn[3]);
        // h1 visibility for next iteration guaranteed by S1(t+1)
    }
    __syncthreads();

    // ================= MLP head: out = W2 @ relu(W1 @ h2 + b1) + b2 =========
    if (tid < NB) {
        float acc = b2[0];
#pragma unroll 1
        for (int u = 0; u < 32; u++) {
            float s = b1[u];
            const float* wr = W1 + u * 64;
#pragma unroll
            for (int k = 0; k < 64; k++) s += wr[k] * h1s[k * HS + tid];
            acc += W2[u] * fmaxf(s, 0.0f);
        }
        out[B0 + tid] = acc;
    }
}

extern "C" void kernel_launch(void* const* d_in, const int* in_sizes, int n_in,
                              void* d_out, int out_size)
{
    const float* x    = (const float*)d_in[0];
    const float* Wih0 = (const float*)d_in[1];
    const float* Whh0 = (const float*)d_in[2];
    const float* bih0 = (const float*)d_in[3];
    const float* bhh0 = (const float*)d_in[4];
    const float* Wih1 = (const float*)d_in[5];
    const float* Whh1 = (const float*)d_in[6];
    const float* bih1 = (const float*)d_in[7];
    const float* bhh1 = (const float*)d_in[8];
    const float* W1   = (const float*)d_in[9];
    const float* b1   = (const float*)d_in[10];
    const float* W2   = (const float*)d_in[11];
    const float* b2   = (const float*)d_in[12];
    float* out = (float*)d_out;

    cudaFuncSetAttribute(stocklstm_kernel,
                         cudaFuncAttributeMaxDynamicSharedMemorySize, SMEM_BYTES);
    stocklstm_kernel<<<B_TOT / NB, NTHR, SMEM_BYTES>>>(
        x, Wih0, Whh0, bih0, bhh0, Wih1, Whh1, bih1, bhh1, W1, b1, W2, b2, out);
}

// round 3
// speedup vs baseline: 1.2606x; 1.2606x over previous
#include <cuda_runtime.h>

#define B_TOT 4096
#define T_LEN 512
#define D_IN  5
#define NB    32          // batches per CTA
#define NTHR  256         // 8 warps: crossbar-optimal (weight-LDS dup = 4x)
#define HS    36          // padded row stride (floats) for h/x state

// shared memory layout (float offsets)
#define OFF_WHH0 0
#define OFF_WIH1 16384
#define OFF_WHH1 32768
#define OFF_WIH0 49152                 // 5*64*4 = 1280
#define OFF_H0A  (49152 + 1280)        // 64*36 = 2304 (h0 buffer 0)
#define OFF_H0B  (OFF_H0A + 2304)      // h0 buffer 1
#define OFF_H1   (OFF_H0B + 2304)
#define OFF_XA   (OFF_H1 + 2304)       // 5*36 = 180 (x buffer 0)
#define OFF_XB   (OFF_XA + 180)
#define SMEM_FLOATS (OFF_XB + 180)     // 57,704 floats
#define SMEM_BYTES  (SMEM_FLOATS * 4)  // 230,816 B (< 232,448 dyn limit)

typedef unsigned long long u64;

union F2U { float2 f; u64 u; };

__device__ __forceinline__ u64 dup2(float x) {
    F2U t; t.f = make_float2(x, x); return t.u;
}
__device__ __forceinline__ float2 unpk(u64 v) {
    F2U t; t.u = v; return t.f;
}
// packed fp32x2 FMA: a.lo += x.lo*w.lo ; a.hi += x.hi*w.hi
__device__ __forceinline__ void fma2(u64& a, u64 x, u64 w) {
    asm("fma.rn.f32x2 %0, %1, %2, %0;" : "+l"(a) : "l"(x), "l"(w));
}

// MUFU.TANH — single MUFU op (measured rel_err impact ~0 in R2)
__device__ __forceinline__ float tanha(float x) {
    float y; asm("tanh.approx.f32 %0, %1;" : "=f"(y) : "f"(x)); return y;
}
__device__ __forceinline__ float sigf(float x) {
    return fmaf(0.5f, tanha(0.5f * x), 0.5f);
}

__global__ void __launch_bounds__(NTHR, 1)
stocklstm_kernel(const float* __restrict__ x,
                 const float* __restrict__ W_ih0, const float* __restrict__ W_hh0,
                 const float* __restrict__ b_ih0, const float* __restrict__ b_hh0,
                 const float* __restrict__ W_ih1, const float* __restrict__ W_hh1,
                 const float* __restrict__ b_ih1, const float* __restrict__ b_hh1,
                 const float* __restrict__ W1,   const float* __restrict__ b1,
                 const float* __restrict__ W2,   const float* __restrict__ b2,
                 float* __restrict__ out)
{
    extern __shared__ float sm[];
    float* whh0 = sm + OFF_WHH0;
    float* wih1 = sm + OFF_WIH1;
    float* whh1 = sm + OFF_WHH1;
    float* wih0 = sm + OFF_WIH0;
    float* h0buf[2] = { sm + OFF_H0A, sm + OFF_H0B };
    float* h1s  = sm + OFF_H1;
    float* xbuf[2] = { sm + OFF_XA, sm + OFF_XB };

    const int tid = threadIdx.x;
    const int j   = tid & 63;   // hidden unit index
    const int bg  = tid >> 6;   // batch group 0..3
    const int bb  = bg * 8;     // first batch (of 8) this thread owns
    const int B0  = blockIdx.x * NB;

    // ---- stage weights, packed [k][j][4 gates] for conflict-free LDS.128 ----
    for (int idx = tid; idx < 256 * 64; idx += NTHR) {
        int g = idx >> 6, k = idx & 63;          // global row-major [G][64]
        int gi = g >> 6, jj = g & 63;            // gate type, unit
        int dst = (k * 64 + jj) * 4 + gi;
        whh0[dst] = W_hh0[idx];
        wih1[dst] = W_ih1[idx];
        whh1[dst] = W_hh1[idx];
    }
    for (int idx = tid; idx < 256 * 5; idx += NTHR) {
        int g = idx / 5, d = idx - 5 * g;
        wih0[(d * 64 + (g & 63)) * 4 + (g >> 6)] = W_ih0[idx];
    }
    for (int idx = tid; idx < 64 * HS; idx += NTHR) {
        h0buf[0][idx] = 0.0f; h1s[idx] = 0.0f;
    }

    // bias pre-sums (b_ih + b_hh), duplicated into both f32x2 lanes
    const u64 bi0 = dup2(b_ih0[j]       + b_hh0[j]);
    const u64 bf0 = dup2(b_ih0[64 + j]  + b_hh0[64 + j]);
    const u64 bg0 = dup2(b_ih0[128 + j] + b_hh0[128 + j]);
    const u64 bo0 = dup2(b_ih0[192 + j] + b_hh0[192 + j]);
    const u64 bi1 = dup2(b_ih1[j]       + b_hh1[j]);
    const u64 bf1 = dup2(b_ih1[64 + j]  + b_hh1[64 + j]);
    const u64 bg1 = dup2(b_ih1[128 + j] + b_hh1[128 + j]);
    const u64 bo1 = dup2(b_ih1[192 + j] + b_hh1[192 + j]);

    float c0[8], c1[8];
#pragma unroll
    for (int p = 0; p < 8; p++) { c0[p] = 0.0f; c1[p] = 0.0f; }

    // ---- x staging: threads 0..159 own (batch xbi, feature xd) ----
    const int xbi = tid / 5;
    const int xd  = tid - xbi * 5;
    const float* xptr = x + (size_t)(B0 + xbi) * (T_LEN * D_IN) + xd;
    float xreg = 0.0f;
    if (tid < 160) {
        xreg = xptr[0];
        xbuf[0][xd * HS + xbi] = xreg;           // stage x[0]
        xreg = xptr[D_IN];                       // prefetch x[1]
    }

    __syncthreads();

    for (int t = 0; t < T_LEN; t++) {
        const int cur = t & 1, nxt = cur ^ 1;
        const float* h0c = h0buf[cur];
        const float* xc  = xbuf[cur];

        // ================= Layer 0 gates (read x[cur], h0[cur]) ===========
        u64 aI[4], aF[4], aG[4], aO[4];
#pragma unroll
        for (int p = 0; p < 4; p++) { aI[p] = bi0; aF[p] = bf0; aG[p] = bg0; aO[p] = bo0; }

#pragma unroll
        for (int d = 0; d < 5; d++) {
            float4 w = *(const float4*)&wih0[(d * 64 + j) * 4];
            u64 wi = dup2(w.x), wf = dup2(w.y), wg = dup2(w.z), wo = dup2(w.w);
            const ulonglong2* xp = (const ulonglong2*)&xc[d * HS + bb];
            ulonglong2 xa = xp[0], xb = xp[1];
            fma2(aI[0], xa.x, wi); fma2(aI[1], xa.y, wi); fma2(aI[2], xb.x, wi); fma2(aI[3], xb.y, wi);
            fma2(aF[0], xa.x, wf); fma2(aF[1], xa.y, wf); fma2(aF[2], xb.x, wf); fma2(aF[3], xb.y, wf);
            fma2(aG[0], xa.x, wg); fma2(aG[1], xa.y, wg); fma2(aG[2], xb.x, wg); fma2(aG[3], xb.y, wg);
            fma2(aO[0], xa.x, wo); fma2(aO[1], xa.y, wo); fma2(aO[2], xb.x, wo); fma2(aO[3], xb.y, wo);
        }
#pragma unroll 8
        for (int k = 0; k < 64; k++) {
            float4 w = *(const float4*)&whh0[(k * 64 + j) * 4];
            u64 wi = dup2(w.x), wf = dup2(w.y), wg = dup2(w.z), wo = dup2(w.w);
            const ulonglong2* hp = (const ulonglong2*)&h0c[k * HS + bb];
            ulonglong2 ha = hp[0], hb = hp[1];
            fma2(aI[0], ha.x, wi); fma2(aI[1], ha.y, wi); fma2(aI[2], hb.x, wi); fma2(aI[3], hb.y, wi);
            fma2(aF[0], ha.x, wf); fma2(aF[1], ha.y, wf); fma2(aF[2], hb.x, wf); fma2(aF[3], hb.y, wf);
            fma2(aG[0], ha.x, wg); fma2(aG[1], ha.y, wg); fma2(aG[2], hb.x, wg); fma2(aG[3], hb.y, wg);
            fma2(aO[0], ha.x, wo); fma2(aO[1], ha.y, wo); fma2(aO[2], hb.x, wo); fma2(aO[3], hb.y, wo);
        }
        // pointwise L0 (c stays in registers) — all MUFU.TANH
        float hn[8];
#pragma unroll
        for (int p = 0; p < 4; p++) {
            float2 vi = unpk(aI[p]), vf = unpk(aF[p]), vg = unpk(aG[p]), vo = unpk(aO[p]);
            float ca = sigf(vf.x) * c0[2 * p]     + sigf(vi.x) * tanha(vg.x);
            float cb = sigf(vf.y) * c0[2 * p + 1] + sigf(vi.y) * tanha(vg.y);
            c0[2 * p] = ca; c0[2 * p + 1] = cb;
            hn[2 * p]     = sigf(vo.x) * tanha(ca);
            hn[2 * p + 1] = sigf(vo.y) * tanha(cb);
        }
        // write NEW h0 into alternate buffer (no WAR hazard -> no sync needed)
        *(float4*)&h0buf[nxt][j * HS + bb]     = make_float4(hn[0], hn[1], hn[2], hn[3]);
        *(float4*)&h0buf[nxt][j * HS + bb + 4] = make_float4(hn[4], hn[5], hn[6], hn[7]);

        // stage x[t+1] into alternate buffer; prefetch x[t+2]
        if (tid < 160) {
            xbuf[nxt][xd * HS + xbi] = xreg;
            int tn = (t + 2 < T_LEN) ? t + 2 : T_LEN - 1;
            xreg = xptr[tn * D_IN];
        }

        __syncthreads();   // S1: new h0 + new x visible; prev-iter h1 store visible

        // ===== Layer 1 gates: recurrent (old h1) + input (new h0) =========
#pragma unroll
        for (int p = 0; p < 4; p++) { aI[p] = bi1; aF[p] = bf1; aG[p] = bg1; aO[p] = bo1; }
#pragma unroll 8
        for (int k = 0; k < 64; k++) {
            float4 w = *(const float4*)&whh1[(k * 64 + j) * 4];
            u64 wi = dup2(w.x), wf = dup2(w.y), wg = dup2(w.z), wo = dup2(w.w);
            const ulonglong2* hp = (const ulonglong2*)&h1s[k * HS + bb];
            ulonglong2 ha = hp[0], hb = hp[1];
            fma2(aI[0], ha.x, wi); fma2(aI[1], ha.y, wi); fma2(aI[2], hb.x, wi); fma2(aI[3], hb.y, wi);
            fma2(aF[0], ha.x, wf); fma2(aF[1], ha.y, wf); fma2(aF[2], hb.x, wf); fma2(aF[3], hb.y, wf);
            fma2(aG[0], ha.x, wg); fma2(aG[1], ha.y, wg); fma2(aG[2], hb.x, wg); fma2(aG[3], hb.y, wg);
            fma2(aO[0], ha.x, wo); fma2(aO[1], ha.y, wo); fma2(aO[2], hb.x, wo); fma2(aO[3], hb.y, wo);
        }
        const float* h0n = h0buf[nxt];
#pragma unroll 8
        for (int k = 0; k < 64; k++) {
            float4 w = *(const float4*)&wih1[(k * 64 + j) * 4];
            u64 wi = dup2(w.x), wf = dup2(w.y), wg = dup2(w.z), wo = dup2(w.w);
            const ulonglong2* hp = (const ulonglong2*)&h0n[k * HS + bb];
            ulonglong2 ha = hp[0], hb = hp[1];
            fma2(aI[0], ha.x, wi); fma2(aI[1], ha.y, wi); fma2(aI[2], hb.x, wi); fma2(aI[3], hb.y, wi);
            fma2(aF[0], ha.x, wf); fma2(aF[1], ha.y, wf); fma2(aF[2], hb.x, wf); fma2(aF[3], hb.y, wf);
            fma2(aG[0], ha.x, wg); fma2(aG[1], ha.y, wg); fma2(aG[2], hb.x, wg); fma2(aG[3], hb.y, wg);
            fma2(aO[0], ha.x, wo); fma2(aO[1], ha.y, wo); fma2(aO[2], hb.x, wo); fma2(aO[3], hb.y, wo);
        }

        // pointwise L1 (register-only; safe before the barrier)
#pragma unroll
        for (int p = 0; p < 4; p++) {
            float2 vi = unpk(aI[p]), vf = unpk(aF[p]), vg = unpk(aG[p]), vo = unpk(aO[p]);
            float ca = sigf(vf.x) * c1[2 * p]     + sigf(vi.x) * tanha(vg.x);
            float cb = sigf(vf.y) * c1[2 * p + 1] + sigf(vi.y) * tanha(vg.y);
            c1[2 * p] = ca; c1[2 * p + 1] = cb;
            hn[2 * p]     = sigf(vo.x) * tanha(ca);
            hn[2 * p + 1] = sigf(vo.y) * tanha(cb);
        }

        __syncthreads();   // S2: all reads of old h1 complete
        *(float4*)&h1s[j * HS + bb]     = make_float4(hn[0], hn[1], hn[2], hn[3]);
        *(float4*)&h1s[j * HS + bb + 4] = make_float4(hn[4], hn[5], hn[6], hn[7]);
        // h1 visibility for next iteration guaranteed by S1(t+1)
    }
    __syncthreads();

    // ================= MLP head: out = W2 @ relu(W1 @ h2 + b1) + b2 =========
    if (tid < NB) {
        float acc = b2[0];
#pragma unroll 1
        for (int u = 0; u < 32; u++) {
            float s = b1[u];
            const float* wr = W1 + u * 64;
#pragma unroll
            for (int k = 0; k < 64; k++) s += wr[k] * h1s[k * HS + tid];
            acc += W2[u] * fmaxf(s, 0.0f);
        }
        out[B0 + tid] = acc;
    }
}

extern "C" void kernel_launch(void* const* d_in, const int* in_sizes, int n_in,
                              void* d_out, int out_size)
{
    const float* x    = (const float*)d_in[0];
    const float* Wih0 = (const float*)d_in[1];
    const float* Whh0 = (const float*)d_in[2];
    const float* bih0 = (const float*)d_in[3];
    const float* bhh0 = (const float*)d_in[4];
    const float* Wih1 = (const float*)d_in[5];
    const float* Whh1 = (const float*)d_in[6];
    const float* bih1 = (const float*)d_in[7];
    const float* bhh1 = (const float*)d_in[8];
    const float* W1   = (const float*)d_in[9];
    const float* b1   = (const float*)d_in[10];
    const float* W2   = (const float*)d_in[11];
    const float* b2   = (const float*)d_in[12];
    float* out = (float*)d_out;

    cudaFuncSetAttribute(stocklstm_kernel,
                         cudaFuncAttributeMaxDynamicSharedMemorySize, SMEM_BYTES);
    stocklstm_kernel<<<B_TOT / NB, NTHR, SMEM_BYTES>>>(
        x, Wih0, Whh0, bih0, bhh0, Wih1, Whh1, bih1, bhh1, W1, b1, W2, b2, out);
}

// round 4
// speedup vs baseline: 1.4631x; 1.1607x over previous
#include <cuda_runtime.h>

#define B_TOT 4096
#define T_LEN 512
#define D_IN  5
#define NB    32          // batches per CTA
#define NTHR  256
#define HS    36          // padded row stride (floats) for h/x state

// shared memory layout (float offsets)
#define OFF_WHH0 0
#define OFF_WIH1 16384
#define OFF_WHH1 32768
#define OFF_WIH0 49152                 // 5*64*4 = 1280
#define OFF_H0   (49152 + 1280)        // 64*36 = 2304
#define OFF_H1   (OFF_H0 + 2304)
#define OFF_X    (OFF_H1 + 2304)       // 5*36 = 180
#define SMEM_FLOATS (OFF_X + 180)
#define SMEM_BYTES  (SMEM_FLOATS * 4)  // 220,880 B

typedef unsigned long long u64;

union F2U { float2 f; u64 u; };

__device__ __forceinline__ u64 dup2(float x) {
    F2U t; t.f = make_float2(x, x); return t.u;
}
__device__ __forceinline__ float2 unpk(u64 v) {
    F2U t; t.u = v; return t.f;
}
// packed fp32x2 FMA: a.lo += x.lo*w.lo ; a.hi += x.hi*w.hi
__device__ __forceinline__ void fma2(u64& a, u64 x, u64 w) {
    asm("fma.rn.f32x2 %0, %1, %2, %0;" : "+l"(a) : "l"(x), "l"(w));
}

// MUFU.TANH — single MUFU op (accuracy validated in R2/R3: rel_err ~7e-7)
__device__ __forceinline__ float tanha(float x) {
    float y; asm("tanh.approx.f32 %0, %1;" : "=f"(y) : "f"(x)); return y;
}
__device__ __forceinline__ float sigf(float x) {
    return fmaf(0.5f, tanha(0.5f * x), 0.5f);
}

__global__ void __launch_bounds__(NTHR, 1)
stocklstm_kernel(const float* __restrict__ x,
                 const float* __restrict__ W_ih0, const float* __restrict__ W_hh0,
                 const float* __restrict__ b_ih0, const float* __restrict__ b_hh0,
                 const float* __restrict__ W_ih1, const float* __restrict__ W_hh1,
                 const float* __restrict__ b_ih1, const float* __restrict__ b_hh1,
                 const float* __restrict__ W1,   const float* __restrict__ b1,
                 const float* __restrict__ W2,   const float* __restrict__ b2,
                 float* __restrict__ out)
{
    extern __shared__ float sm[];
    float* whh0 = sm + OFF_WHH0;
    float* wih1 = sm + OFF_WIH1;
    float* whh1 = sm + OFF_WHH1;
    float* wih0 = sm + OFF_WIH0;
    float* h0s  = sm + OFF_H0;
    float* h1s  = sm + OFF_H1;
    float* xs   = sm + OFF_X;

    const int tid = threadIdx.x;
    const int j   = tid & 63;   // hidden unit index
    const int bg  = tid >> 6;   // batch group 0..3
    const int bb  = bg * 8;     // first batch (of 8) this thread owns
    const int B0  = blockIdx.x * NB;

    // ---- stage weights, packed [k][j][4 gates] for conflict-free LDS.128 ----
    for (int idx = tid; idx < 256 * 64; idx += NTHR) {
        int g = idx >> 6, k = idx & 63;          // global row-major [G][64]
        int gi = g >> 6, jj = g & 63;            // gate type, unit
        int dst = (k * 64 + jj) * 4 + gi;
        whh0[dst] = W_hh0[idx];
        wih1[dst] = W_ih1[idx];
        whh1[dst] = W_hh1[idx];
    }
    for (int idx = tid; idx < 256 * 5; idx += NTHR) {
        int g = idx / 5, d = idx - 5 * g;
        wih0[(d * 64 + (g & 63)) * 4 + (g >> 6)] = W_ih0[idx];
    }
    for (int idx = tid; idx < 64 * HS; idx += NTHR) { h0s[idx] = 0.0f; h1s[idx] = 0.0f; }

    // bias pre-sums (b_ih + b_hh), duplicated into both f32x2 lanes
    const u64 bi0 = dup2(b_ih0[j]       + b_hh0[j]);
    const u64 bf0 = dup2(b_ih0[64 + j]  + b_hh0[64 + j]);
    const u64 bg0 = dup2(b_ih0[128 + j] + b_hh0[128 + j]);
    const u64 bo0 = dup2(b_ih0[192 + j] + b_hh0[192 + j]);
    const u64 bi1 = dup2(b_ih1[j]       + b_hh1[j]);
    const u64 bf1 = dup2(b_ih1[64 + j]  + b_hh1[64 + j]);
    const u64 bg1 = dup2(b_ih1[128 + j] + b_hh1[128 + j]);
    const u64 bo1 = dup2(b_ih1[192 + j] + b_hh1[192 + j]);

    float c0[8], c1[8];
#pragma unroll
    for (int p = 0; p < 8; p++) { c0[p] = 0.0f; c1[p] = 0.0f; }

    // ---- x prefetch registers (threads 0..159: batch bi, feature d) ----
    const int xbi = tid / 5;
    const int xd  = tid - xbi * 5;
    const float* xptr = x + (size_t)(B0 + xbi) * (T_LEN * D_IN) + xd;
    float xreg = 0.0f;
    if (tid < 160) xreg = xptr[0];

    __syncthreads();

    for (int t = 0; t < T_LEN; t++) {
        if (tid < 160) xs[xd * HS + xbi] = xreg;
        __syncthreads();                    // (A) x[t] staged; prev h1 visible
        if (tid < 160) {
            int tn = (t + 1 < T_LEN) ? t + 1 : t;
            xreg = xptr[tn * D_IN];         // prefetch next step (latency hidden)
        }

        // ================= Layer 0 gates =================
        u64 aI[4], aF[4], aG[4], aO[4];
#pragma unroll
        for (int p = 0; p < 4; p++) { aI[p] = bi0; aF[p] = bf0; aG[p] = bg0; aO[p] = bo0; }

#pragma unroll
        for (int d = 0; d < 5; d++) {
            float4 w = *(const float4*)&wih0[(d * 64 + j) * 4];
            u64 wi = dup2(w.x), wf = dup2(w.y), wg = dup2(w.z), wo = dup2(w.w);
            const ulonglong2* xp = (const ulonglong2*)&xs[d * HS + bb];
            ulonglong2 xa = xp[0], xb = xp[1];
            fma2(aI[0], xa.x, wi); fma2(aI[1], xa.y, wi); fma2(aI[2], xb.x, wi); fma2(aI[3], xb.y, wi);
            fma2(aF[0], xa.x, wf); fma2(aF[1], xa.y, wf); fma2(aF[2], xb.x, wf); fma2(aF[3], xb.y, wf);
            fma2(aG[0], xa.x, wg); fma2(aG[1], xa.y, wg); fma2(aG[2], xb.x, wg); fma2(aG[3], xb.y, wg);
            fma2(aO[0], xa.x, wo); fma2(aO[1], xa.y, wo); fma2(aO[2], xb.x, wo); fma2(aO[3], xb.y, wo);
        }
#pragma unroll 4
        for (int k = 0; k < 64; k++) {
            float4 w = *(const float4*)&whh0[(k * 64 + j) * 4];
            u64 wi = dup2(w.x), wf = dup2(w.y), wg = dup2(w.z), wo = dup2(w.w);
            const ulonglong2* hp = (const ulonglong2*)&h0s[k * HS + bb];
            ulonglong2 ha = hp[0], hb = hp[1];
            fma2(aI[0], ha.x, wi); fma2(aI[1], ha.y, wi); fma2(aI[2], hb.x, wi); fma2(aI[3], hb.y, wi);
            fma2(aF[0], ha.x, wf); fma2(aF[1], ha.y, wf); fma2(aF[2], hb.x, wf); fma2(aF[3], hb.y, wf);
            fma2(aG[0], ha.x, wg); fma2(aG[1], ha.y, wg); fma2(aG[2], hb.x, wg); fma2(aG[3], hb.y, wg);
            fma2(aO[0], ha.x, wo); fma2(aO[1], ha.y, wo); fma2(aO[2], hb.x, wo); fma2(aO[3], hb.y, wo);
        }
        // pointwise L0 (c stays in registers) — MUFU.TANH only
        float hn[8];
#pragma unroll
        for (int p = 0; p < 4; p++) {
            float2 vi = unpk(aI[p]), vf = unpk(aF[p]), vg = unpk(aG[p]), vo = unpk(aO[p]);
            float ca = sigf(vf.x) * c0[2 * p]     + sigf(vi.x) * tanha(vg.x);
            float cb = sigf(vf.y) * c0[2 * p + 1] + sigf(vi.y) * tanha(vg.y);
            c0[2 * p] = ca; c0[2 * p + 1] = cb;
            hn[2 * p]     = sigf(vo.x) * tanha(ca);
            hn[2 * p + 1] = sigf(vo.y) * tanha(cb);
        }
        __syncthreads();                    // (B) everyone done reading old h0
        *(float4*)&h0s[j * HS + bb]     = make_float4(hn[0], hn[1], hn[2], hn[3]);
        *(float4*)&h0s[j * HS + bb + 4] = make_float4(hn[4], hn[5], hn[6], hn[7]);

        // ================= Layer 1: recurrent part (old h1) =================
#pragma unroll
        for (int p = 0; p < 4; p++) { aI[p] = bi1; aF[p] = bf1; aG[p] = bg1; aO[p] = bo1; }
#pragma unroll 4
        for (int k = 0; k < 64; k++) {
            float4 w = *(const float4*)&whh1[(k * 64 + j) * 4];
            u64 wi = dup2(w.x), wf = dup2(w.y), wg = dup2(w.z), wo = dup2(w.w);
            const ulonglong2* hp = (const ulonglong2*)&h1s[k * HS + bb];
            ulonglong2 ha = hp[0], hb = hp[1];
            fma2(aI[0], ha.x, wi); fma2(aI[1], ha.y, wi); fma2(aI[2], hb.x, wi); fma2(aI[3], hb.y, wi);
            fma2(aF[0], ha.x, wf); fma2(aF[1], ha.y, wf); fma2(aF[2], hb.x, wf); fma2(aF[3], hb.y, wf);
            fma2(aG[0], ha.x, wg); fma2(aG[1], ha.y, wg); fma2(aG[2], hb.x, wg); fma2(aG[3], hb.y, wg);
            fma2(aO[0], ha.x, wo); fma2(aO[1], ha.y, wo); fma2(aO[2], hb.x, wo); fma2(aO[3], hb.y, wo);
        }
        __syncthreads();                    // (C) new h0 visible; h1 reads done

        // ================= Layer 1: input part (new h0) =================
#pragma unroll 4
        for (int k = 0; k < 64; k++) {
            float4 w = *(const float4*)&wih1[(k * 64 + j) * 4];
            u64 wi = dup2(w.x), wf = dup2(w.y), wg = dup2(w.z), wo = dup2(w.w);
            const ulonglong2* hp = (const ulonglong2*)&h0s[k * HS + bb];
            ulonglong2 ha = hp[0], hb = hp[1];
            fma2(aI[0], ha.x, wi); fma2(aI[1], ha.y, wi); fma2(aI[2], hb.x, wi); fma2(aI[3], hb.y, wi);
            fma2(aF[0], ha.x, wf); fma2(aF[1], ha.y, wf); fma2(aF[2], hb.x, wf); fma2(aF[3], hb.y, wf);
            fma2(aG[0], ha.x, wg); fma2(aG[1], ha.y, wg); fma2(aG[2], hb.x, wg); fma2(aG[3], hb.y, wg);
            fma2(aO[0], ha.x, wo); fma2(aO[1], ha.y, wo); fma2(aO[2], hb.x, wo); fma2(aO[3], hb.y, wo);
        }
        // pointwise L1 — MUFU.TANH only
#pragma unroll
        for (int p = 0; p < 4; p++) {
            float2 vi = unpk(aI[p]), vf = unpk(aF[p]), vg = unpk(aG[p]), vo = unpk(aO[p]);
            float ca = sigf(vf.x) * c1[2 * p]     + sigf(vi.x) * tanha(vg.x);
            float cb = sigf(vf.y) * c1[2 * p + 1] + sigf(vi.y) * tanha(vg.y);
            c1[2 * p] = ca; c1[2 * p + 1] = cb;
            hn[2 * p]     = sigf(vo.x) * tanha(ca);
            hn[2 * p + 1] = sigf(vo.y) * tanha(cb);
        }
        *(float4*)&h1s[j * HS + bb]     = make_float4(hn[0], hn[1], hn[2], hn[3]);
        *(float4*)&h1s[j * HS + bb + 4] = make_float4(hn[4], hn[5], hn[6], hn[7]);
        // visibility of h1 for next iteration guaranteed by sync (A)
    }
    __syncthreads();

    // ================= MLP head: out = W2 @ relu(W1 @ h2 + b1) + b2 =========
    if (tid < NB) {
        float acc = b2[0];
#pragma unroll 1
        for (int u = 0; u < 32; u++) {
            float s = b1[u];
            const float* wr = W1 + u * 64;
#pragma unroll
            for (int k = 0; k < 64; k++) s += wr[k] * h1s[k * HS + tid];
            acc += W2[u] * fmaxf(s, 0.0f);
        }
        out[B0 + tid] = acc;
    }
}

extern "C" void kernel_launch(void* const* d_in, const int* in_sizes, int n_in,
                              void* d_out, int out_size)
{
    const float* x    = (const float*)d_in[0];
    const float* Wih0 = (const float*)d_in[1];
    const float* Whh0 = (const float*)d_in[2];
    const float* bih0 = (const float*)d_in[3];
    const float* bhh0 = (const float*)d_in[4];
    const float* Wih1 = (const float*)d_in[5];
    const float* Whh1 = (const float*)d_in[6];
    const float* bih1 = (const float*)d_in[7];
    const float* bhh1 = (const float*)d_in[8];
    const float* W1   = (const float*)d_in[9];
    const float* b1   = (const float*)d_in[10];
    const float* W2   = (const float*)d_in[11];
    const float* b2   = (const float*)d_in[12];
    float* out = (float*)d_out;

    cudaFuncSetAttribute(stocklstm_kernel,
                         cudaFuncAttributeMaxDynamicSharedMemorySize, SMEM_BYTES);
    stocklstm_kernel<<<B_TOT / NB, NTHR, SMEM_BYTES>>>(
        x, Wih0, Whh0, bih0, bhh0, Wih1, Whh1, bih1, bhh1, W1, b1, W2, b2, out);
}

// round 5
// speedup vs baseline: 1.4651x; 1.0013x over previous
#include <cuda_runtime.h>

#define B_TOT 4096
#define T_LEN 512
#define D_IN  5
#define NB    32          // batches per CTA
#define NTHR  256
#define HS    36          // padded row stride (floats) for h/x state

// shared memory layout (float offsets)
#define OFF_WHH0 0
#define OFF_WIH1 16384
#define OFF_WHH1 32768
#define OFF_WIH0 49152                 // 5*64*4 = 1280
#define OFF_H0   (49152 + 1280)        // 64*36 = 2304
#define OFF_H1   (OFF_H0 + 2304)
#define OFF_X    (OFF_H1 + 2304)       // 5*36 = 180
#define SMEM_FLOATS (OFF_X + 180)
#define SMEM_BYTES  (SMEM_FLOATS * 4)  // 220,880 B

typedef unsigned long long u64;

union F2U { float2 f; u64 u; };

__device__ __forceinline__ u64 dup2(float x) {
    F2U t; t.f = make_float2(x, x); return t.u;
}
__device__ __forceinline__ float2 unpk(u64 v) {
    F2U t; t.u = v; return t.f;
}
// packed fp32x2 FMA: a.lo += x.lo*w.lo ; a.hi += x.hi*w.hi
__device__ __forceinline__ void fma2(u64& a, u64 x, u64 w) {
    asm("fma.rn.f32x2 %0, %1, %2, %0;" : "+l"(a) : "l"(x), "l"(w));
}

// MUFU.TANH — single MUFU op (accuracy validated in R2/R3: rel_err ~7e-7)
__device__ __forceinline__ float tanha(float x) {
    float y; asm("tanh.approx.f32 %0, %1;" : "=f"(y) : "f"(x)); return y;
}
__device__ __forceinline__ float sigf(float x) {
    return fmaf(0.5f, tanha(0.5f * x), 0.5f);
}

__global__ void __launch_bounds__(NTHR, 1)
stocklstm_kernel(const float* __restrict__ x,
                 const float* __restrict__ W_ih0, const float* __restrict__ W_hh0,
                 const float* __restrict__ b_ih0, const float* __restrict__ b_hh0,
                 const float* __restrict__ W_ih1, const float* __restrict__ W_hh1,
                 const float* __restrict__ b_ih1, const float* __restrict__ b_hh1,
                 const float* __restrict__ W1,   const float* __restrict__ b1,
                 const float* __restrict__ W2,   const float* __restrict__ b2,
                 float* __restrict__ out)
{
    extern __shared__ float sm[];
    float* whh0 = sm + OFF_WHH0;
    float* wih1 = sm + OFF_WIH1;
    float* whh1 = sm + OFF_WHH1;
    float* wih0 = sm + OFF_WIH0;
    float* h0s  = sm + OFF_H0;
    float* h1s  = sm + OFF_H1;
    float* xs   = sm + OFF_X;

    const int tid = threadIdx.x;
    const int j   = tid & 63;   // hidden unit index
    const int bg  = tid >> 6;   // batch group 0..3
    const int bb  = bg * 8;     // first batch (of 8) this thread owns
    const int B0  = blockIdx.x * NB;

    // ---- stage weights, packed [k][j][4 gates] for conflict-free LDS.128 ----
    for (int idx = tid; idx < 256 * 64; idx += NTHR) {
        int g = idx >> 6, k = idx & 63;          // global row-major [G][64]
        int gi = g >> 6, jj = g & 63;            // gate type, unit
        int dst = (k * 64 + jj) * 4 + gi;
        whh0[dst] = W_hh0[idx];
        wih1[dst] = W_ih1[idx];
        whh1[dst] = W_hh1[idx];
    }
    for (int idx = tid; idx < 256 * 5; idx += NTHR) {
        int g = idx / 5, d = idx - 5 * g;
        wih0[(d * 64 + (g & 63)) * 4 + (g >> 6)] = W_ih0[idx];
    }
    for (int idx = tid; idx < 64 * HS; idx += NTHR) { h0s[idx] = 0.0f; h1s[idx] = 0.0f; }

    // bias pre-sums (b_ih + b_hh), duplicated into both f32x2 lanes
    const u64 bi0 = dup2(b_ih0[j]       + b_hh0[j]);
    const u64 bf0 = dup2(b_ih0[64 + j]  + b_hh0[64 + j]);
    const u64 bg0 = dup2(b_ih0[128 + j] + b_hh0[128 + j]);
    const u64 bo0 = dup2(b_ih0[192 + j] + b_hh0[192 + j]);
    const u64 bi1 = dup2(b_ih1[j]       + b_hh1[j]);
    const u64 bf1 = dup2(b_ih1[64 + j]  + b_hh1[64 + j]);
    const u64 bg1 = dup2(b_ih1[128 + j] + b_hh1[128 + j]);
    const u64 bo1 = dup2(b_ih1[192 + j] + b_hh1[192 + j]);

    float c0[8], c1[8];
#pragma unroll
    for (int p = 0; p < 8; p++) { c0[p] = 0.0f; c1[p] = 0.0f; }

    // ---- x prefetch registers (threads 0..159: batch bi, feature d) ----
    const int xbi = tid / 5;
    const int xd  = tid - xbi * 5;
    const float* xptr = x + (size_t)(B0 + xbi) * (T_LEN * D_IN) + xd;
    float xreg = 0.0f;
    if (tid < 160) xreg = xptr[0];

    __syncthreads();

    for (int t = 0; t < T_LEN; t++) {
        if (tid < 160) xs[xd * HS + xbi] = xreg;
        __syncthreads();                    // (A) x[t] staged; prev h1 visible
        if (tid < 160) {
            int tn = (t + 1 < T_LEN) ? t + 1 : t;
            xreg = xptr[tn * D_IN];         // prefetch next step (latency hidden)
        }

        // ================= Layer 0 gates =================
        u64 aI[4], aF[4], aG[4], aO[4];
#pragma unroll
        for (int p = 0; p < 4; p++) { aI[p] = bi0; aF[p] = bf0; aG[p] = bg0; aO[p] = bo0; }

#pragma unroll
        for (int d = 0; d < 5; d++) {
            float4 w = *(const float4*)&wih0[(d * 64 + j) * 4];
            u64 wi = dup2(w.x), wf = dup2(w.y), wg = dup2(w.z), wo = dup2(w.w);
            const ulonglong2* xp = (const ulonglong2*)&xs[d * HS + bb];
            ulonglong2 xa = xp[0], xb = xp[1];
            fma2(aI[0], xa.x, wi); fma2(aI[1], xa.y, wi); fma2(aI[2], xb.x, wi); fma2(aI[3], xb.y, wi);
            fma2(aF[0], xa.x, wf); fma2(aF[1], xa.y, wf); fma2(aF[2], xb.x, wf); fma2(aF[3], xb.y, wf);
            fma2(aG[0], xa.x, wg); fma2(aG[1], xa.y, wg); fma2(aG[2], xb.x, wg); fma2(aG[3], xb.y, wg);
            fma2(aO[0], xa.x, wo); fma2(aO[1], xa.y, wo); fma2(aO[2], xb.x, wo); fma2(aO[3], xb.y, wo);
        }
#pragma unroll 4
        for (int k = 0; k < 64; k++) {
            float4 w = *(const float4*)&whh0[(k * 64 + j) * 4];
            u64 wi = dup2(w.x), wf = dup2(w.y), wg = dup2(w.z), wo = dup2(w.w);
            const ulonglong2* hp = (const ulonglong2*)&h0s[k * HS + bb];
            ulonglong2 ha = hp[0], hb = hp[1];
            fma2(aI[0], ha.x, wi); fma2(aI[1], ha.y, wi); fma2(aI[2], hb.x, wi); fma2(aI[3], hb.y, wi);
            fma2(aF[0], ha.x, wf); fma2(aF[1], ha.y, wf); fma2(aF[2], hb.x, wf); fma2(aF[3], hb.y, wf);
            fma2(aG[0], ha.x, wg); fma2(aG[1], ha.y, wg); fma2(aG[2], hb.x, wg); fma2(aG[3], hb.y, wg);
            fma2(aO[0], ha.x, wo); fma2(aO[1], ha.y, wo); fma2(aO[2], hb.x, wo); fma2(aO[3], hb.y, wo);
        }
        // pointwise L0 (c stays in registers) — MUFU.TANH only
        float hn[8];
#pragma unroll
        for (int p = 0; p < 4; p++) {
            float2 vi = unpk(aI[p]), vf = unpk(aF[p]), vg = unpk(aG[p]), vo = unpk(aO[p]);
            float ca = sigf(vf.x) * c0[2 * p]     + sigf(vi.x) * tanha(vg.x);
            float cb = sigf(vf.y) * c0[2 * p + 1] + sigf(vi.y) * tanha(vg.y);
            c0[2 * p] = ca; c0[2 * p + 1] = cb;
            hn[2 * p]     = sigf(vo.x) * tanha(ca);
            hn[2 * p + 1] = sigf(vo.y) * tanha(cb);
        }
        __syncthreads();                    // (B) everyone done reading old h0
        *(float4*)&h0s[j * HS + bb]     = make_float4(hn[0], hn[1], hn[2], hn[3]);
        *(float4*)&h0s[j * HS + bb + 4] = make_float4(hn[4], hn[5], hn[6], hn[7]);

        // ================= Layer 1: recurrent part (old h1) =================
#pragma unroll
        for (int p = 0; p < 4; p++) { aI[p] = bi1; aF[p] = bf1; aG[p] = bg1; aO[p] = bo1; }
#pragma unroll 4
        for (int k = 0; k < 64; k++) {
            float4 w = *(const float4*)&whh1[(k * 64 + j) * 4];
            u64 wi = dup2(w.x), wf = dup2(w.y), wg = dup2(w.z), wo = dup2(w.w);
            const ulonglong2* hp = (const ulonglong2*)&h1s[k * HS + bb];
            ulonglong2 ha = hp[0], hb = hp[1];
            fma2(aI[0], ha.x, wi); fma2(aI[1], ha.y, wi); fma2(aI[2], hb.x, wi); fma2(aI[3], hb.y, wi);
            fma2(aF[0], ha.x, wf); fma2(aF[1], ha.y, wf); fma2(aF[2], hb.x, wf); fma2(aF[3], hb.y, wf);
            fma2(aG[0], ha.x, wg); fma2(aG[1], ha.y, wg); fma2(aG[2], hb.x, wg); fma2(aG[3], hb.y, wg);
            fma2(aO[0], ha.x, wo); fma2(aO[1], ha.y, wo); fma2(aO[2], hb.x, wo); fma2(aO[3], hb.y, wo);
        }
        __syncthreads();                    // (C) new h0 visible; h1 reads done

        // ================= Layer 1: input part (new h0) =================
#pragma unroll 4
        for (int k = 0; k < 64; k++) {
            float4 w = *(const float4*)&wih1[(k * 64 + j) * 4];
            u64 wi = dup2(w.x), wf = dup2(w.y), wg = dup2(w.z), wo = dup2(w.w);
            const ulonglong2* hp = (const ulonglong2*)&h0s[k * HS + bb];
            ulonglong2 ha = hp[0], hb = hp[1];
            fma2(aI[0], ha.x, wi); fma2(aI[1], ha.y, wi); fma2(aI[2], hb.x, wi); fma2(aI[3], hb.y, wi);
            fma2(aF[0], ha.x, wf); fma2(aF[1], ha.y, wf); fma2(aF[2], hb.x, wf); fma2(aF[3], hb.y, wf);
            fma2(aG[0], ha.x, wg); fma2(aG[1], ha.y, wg); fma2(aG[2], hb.x, wg); fma2(aG[3], hb.y, wg);
            fma2(aO[0], ha.x, wo); fma2(aO[1], ha.y, wo); fma2(aO[2], hb.x, wo); fma2(aO[3], hb.y, wo);
        }
        // pointwise L1 — MUFU.TANH only
#pragma unroll
        for (int p = 0; p < 4; p++) {
            float2 vi = unpk(aI[p]), vf = unpk(aF[p]), vg = unpk(aG[p]), vo = unpk(aO[p]);
            float ca = sigf(vf.x) * c1[2 * p]     + sigf(vi.x) * tanha(vg.x);
            float cb = sigf(vf.y) * c1[2 * p + 1] + sigf(vi.y) * tanha(vg.y);
            c1[2 * p] = ca; c1[2 * p + 1] = cb;
            hn[2 * p]     = sigf(vo.x) * tanha(ca);
            hn[2 * p + 1] = sigf(vo.y) * tanha(cb);
        }
        *(float4*)&h1s[j * HS + bb]     = make_float4(hn[0], hn[1], hn[2], hn[3]);
        *(float4*)&h1s[j * HS + bb + 4] = make_float4(hn[4], hn[5], hn[6], hn[7]);
        // visibility of h1 for next iteration guaranteed by sync (A)
    }
    __syncthreads();

    // ================= MLP head: out = W2 @ relu(W1 @ h2 + b1) + b2 =========
    if (tid < NB) {
        float acc = b2[0];
#pragma unroll 1
        for (int u = 0; u < 32; u++) {
            float s = b1[u];
            const float* wr = W1 + u * 64;
#pragma unroll
            for (int k = 0; k < 64; k++) s += wr[k] * h1s[k * HS + tid];
            acc += W2[u] * fmaxf(s, 0.0f);
        }
        out[B0 + tid] = acc;
    }
}

extern "C" void kernel_launch(void* const* d_in, const int* in_sizes, int n_in,
                              void* d_out, int out_size)
{
    const float* x    = (const float*)d_in[0];
    const float* Wih0 = (const float*)d_in[1];
    const float* Whh0 = (const float*)d_in[2];
    const float* bih0 = (const float*)d_in[3];
    const float* bhh0 = (const float*)d_in[4];
    const float* Wih1 = (const float*)d_in[5];
    const float* Whh1 = (const float*)d_in[6];
    const float* bih1 = (const float*)d_in[7];
    const float* bhh1 = (const float*)d_in[8];
    const float* W1   = (const float*)d_in[9];
    const float* b1   = (const float*)d_in[10];
    const float* W2   = (const float*)d_in[11];
    const float* b2   = (const float*)d_in[12];
    float* out = (float*)d_out;

    cudaFuncSetAttribute(stocklstm_kernel,
                         cudaFuncAttributeMaxDynamicSharedMemorySize, SMEM_BYTES);
    stocklstm_kernel<<<B_TOT / NB, NTHR, SMEM_BYTES>>>(
        x, Wih0, Whh0, bih0, bhh0, Wih1, Whh1, bih1, bhh1, W1, b1, W2, b2, out);
}